// round 6
// baseline (speedup 1.0000x reference)
#include <cuda_runtime.h>
#include <cstdint>

// ---------------------------------------------------------------------------
// PConvLinear via mma.sync tf32 (m16n8k8).
//   out[p,o] = bias[o] + sum_f P[p,f] * W[o,f]
//   P[p, c*16+m] = sum_{k<16} feat[p,k,c] * wn[p,k,m]
// Prep kernel: W -> tf32 B-fragments in gmem (exact ldmatrix replay).
// Main: 256 thr / 64 pts / 8 warps (2x4 grid, 32p x 32o), 2 CTAs/SM,
//       wn register-resident, 34 chunks of 32 f, 1 sync per chunk.
// ---------------------------------------------------------------------------

#define NPTS 120000
#define NB   60000
#define TPB  64
#define THREADS 256
#define GRID (NPTS / TPB)      // 1875 exactly
#define NCHUNK 34

#define TSTRIDE 36             // padded float stride of tf32 tiles
#define TILE_FL (64 * TSTRIDE) // 2304 floats per P-tile buffer

// smem layout (float offsets)
#define OFF_PT   0                    // 2 x 2304  P tf32 [p][f]
#define OFF_G    (2 * TILE_FL)        // 8192: feats [c*16+k][64p] / wn scratch
#define OFF_I    (2 * TILE_FL + 8192) // 1024 ints neighbor inds
#define OFF_BIAS (OFF_I + 1024)       // 128
#define SMEM_FLOATS (OFF_BIAS + 128)
#define SMEM_BYTES (SMEM_FLOATS * 4)  // 55,808 B -> 2 CTAs/SM

// wn staging: XOR-swizzled column to avoid 32-way STS conflicts
#define WNC(r, p) ((r) * 64 + ((p) ^ (((r) >> 2) & 31)))

// W fragments: [cg 34][wn4 4][lane 32][reg 32]
__device__ float Wfrag[34 * 4 * 32 * 32];

__device__ __forceinline__ uint32_t smem_u32(const void* p) {
    uint32_t a;
    asm("{ .reg .u64 t; cvta.to.shared.u64 t, %1; cvt.u32.u64 %0, t; }"
        : "=r"(a) : "l"(p));
    return a;
}
__device__ __forceinline__ uint32_t cvt_tf32(float f) {
    uint32_t r; asm("cvt.rna.tf32.f32 %0, %1;" : "=r"(r) : "f"(f)); return r;
}
__device__ __forceinline__ unsigned long long pack2(float lo, float hi) {
    unsigned long long r;
    asm("mov.b64 %0, {%1, %2};" : "=l"(r) : "f"(lo), "f"(hi));
    return r;
}
__device__ __forceinline__ void unpack2(unsigned long long v, float& lo, float& hi) {
    asm("mov.b64 {%0, %1}, %2;" : "=f"(lo), "=f"(hi) : "l"(v));
}
__device__ __forceinline__ void fma2(unsigned long long& d,
                                     unsigned long long a, unsigned long long b) {
    asm("fma.rn.f32x2 %0, %1, %2, %0;" : "+l"(d) : "l"(a), "l"(b));
}
__device__ __forceinline__ void ldsm4(uint32_t r[4], uint32_t addr) {
    asm volatile("ldmatrix.sync.aligned.m8n8.x4.shared.b16 {%0,%1,%2,%3}, [%4];"
                 : "=r"(r[0]), "=r"(r[1]), "=r"(r[2]), "=r"(r[3]) : "r"(addr));
}
__device__ __forceinline__ void mma8(float c[4], const uint32_t a[4],
                                     uint32_t b0, uint32_t b1) {
    asm volatile(
        "mma.sync.aligned.m16n8k8.row.col.f32.tf32.tf32.f32 "
        "{%0,%1,%2,%3}, {%4,%5,%6,%7}, {%8,%9}, {%0,%1,%2,%3};"
        : "+f"(c[0]), "+f"(c[1]), "+f"(c[2]), "+f"(c[3])
        : "r"(a[0]), "r"(a[1]), "r"(a[2]), "r"(a[3]), "r"(b0), "r"(b1));
}

// ---- prep: replay R4's W staging + ldmatrix once; store fragments ----
extern "C" __global__ void __launch_bounds__(128, 1)
prep_kernel(const float* __restrict__ W) {
    __shared__ float ws[128 * TSTRIDE];
    const int cg = blockIdx.x;
    const int t  = threadIdx.x;
    const int l  = t & 31;
    const int w  = t >> 5;               // wn4 this warp produces
    const int f0 = cg * 32;

    #pragma unroll
    for (int j = 0; j < 8; ++j) {
        int f = f0 + j * 4;
        float4 v = (f < 1072)
            ? *(const float4*)(W + (size_t)t * 1072 + f)
            : make_float4(0.f, 0.f, 0.f, 0.f);
        *(uint4*)(ws + t * TSTRIDE + j * 4) =
            make_uint4(cvt_tf32(v.x), cvt_tf32(v.y), cvt_tf32(v.z), cvt_tf32(v.w));
    }
    __syncthreads();

    const uint32_t bBase = smem_u32(ws) +
        (uint32_t)((w * 32 + (l & 7) + ((l & 16) ? 8 : 0)) * TSTRIDE
                   + ((l & 8) ? 4 : 0)) * 4;
    float* dst = Wfrag + (((size_t)cg * 4 + w) * 32 + l) * 32;
    #pragma unroll
    for (int ks = 0; ks < 4; ++ks)
        #pragma unroll
        for (int np = 0; np < 2; ++np) {
            uint32_t b[4];
            ldsm4(b, bBase + np * 16 * TSTRIDE * 4 + ks * 32);
            *(uint4*)(dst + ks * 8 + np * 4) = make_uint4(b[0], b[1], b[2], b[3]);
        }
}

// ---- main ----
extern "C" __global__ void __launch_bounds__(THREADS, 2)
pcl_kernel(const float* __restrict__ xin,   // [2,60000,64]
           const int*   __restrict__ nbr,   // [2,60000,16]
           const float* __restrict__ wng,   // [2,60000,16,16]
           const float* __restrict__ addf,  // [2,60000,16,3]
           const float* __restrict__ bias,  // [128]
           float*       __restrict__ out)   // [2,60000,128]
{
    extern __shared__ __align__(16) float sm[];
    float* gs   = sm + OFF_G;
    int*   inds = (int*)(sm + OFF_I);

    const uint32_t smb = smem_u32(sm);
    const int t    = threadIdx.x;
    const int wid  = t >> 5;
    const int l    = t & 31;
    const int base = blockIdx.x * TPB;
    const int p    = t & 63;           // P-compute: point
    const int mq   = t >> 6;           // P-compute: m-quad (4 m)

    // MMA roles: warp grid 2(m) x 4(n); each warp 32p x 32o
    const int wm   = wid & 1;
    const int wn4  = wid >> 1;
    const uint32_t aBase = smb + (uint32_t)(OFF_PT + (wm * 32 + (l & 15)) * TSTRIDE
                                            + ((l & 16) ? 4 : 0)) * 4;
    const float* bq = Wfrag + ((size_t)wn4 * 32 + l) * 32;  // + cg*4096

    if (t < 128) sm[OFF_BIAS + t] = bias[t];

    // ---- neighbor indices: 64 pts x 16 ----
    {
        int pt = base + (t >> 2);
        ((int4*)inds)[t] = *(const int4*)(nbr + (size_t)pt * 16 + (size_t)(t & 3) * 4);
    }

    // ---- stage wn (two halves through gs, XOR-swizzled), into registers ----
    unsigned long long wn2[16][2];
    #pragma unroll
    for (int h = 0; h < 2; ++h) {
        __syncthreads();
        #pragma unroll
        for (int rep = 0; rep < 8; ++rep) {
            int lin = rep * 1024 + t * 4;       // 0..8191
            int pp  = lin >> 7;                 // 0..63
            int r   = lin & 127;                // k*16+m, multiple of 4
            int pid = base + pp;
            float4 v = *(const float4*)(wng + (size_t)pid * 256 + h * 128 + r);
            gs[WNC(r + 0, pp)] = v.x;
            gs[WNC(r + 1, pp)] = v.y;
            gs[WNC(r + 2, pp)] = v.z;
            gs[WNC(r + 3, pp)] = v.w;
        }
        __syncthreads();
        #pragma unroll
        for (int k = 0; k < 8; ++k)
            #pragma unroll
            for (int j2 = 0; j2 < 2; ++j2) {
                int r0 = k * 16 + mq * 4 + j2 * 2;
                float lo = gs[WNC(r0 + 0, p)];
                float hi = gs[WNC(r0 + 1, p)];
                wn2[h * 8 + k][j2] = pack2(lo, hi);
            }
    }

    float acc[2][4][4];
    #pragma unroll
    for (int i = 0; i < 2; ++i)
        #pragma unroll
        for (int j = 0; j < 4; ++j)
            #pragma unroll
            for (int q = 0; q < 4; ++q) acc[i][j][q] = 0.f;

    int cg = 0;
    for (int gidx = 0; gidx < 9; ++gidx) {
        // ---- stage gathered feats gs[(c*16+k)][p]: 8 ch x 16 k x 64 p ----
        __syncthreads();
        #pragma unroll
        for (int rep = 0; rep < 4; ++rep) {
            int v  = rep * 256 + t;             // 0..1023
            int pp = v & 63, kk = v >> 6;       // kk 0..15
            int pid = base + pp;
            if (gidx < 8) {
                int nb   = inds[pp * 16 + kk];
                int brow = (pid >= NB) ? NB : 0;
                const float4* src =
                    (const float4*)(xin + ((size_t)brow + nb) * 64 + gidx * 8);
                float4 a = src[0], b4 = src[1];
                gs[(0 * 16 + kk) * 64 + pp] = a.x;
                gs[(1 * 16 + kk) * 64 + pp] = a.y;
                gs[(2 * 16 + kk) * 64 + pp] = a.z;
                gs[(3 * 16 + kk) * 64 + pp] = a.w;
                gs[(4 * 16 + kk) * 64 + pp] = b4.x;
                gs[(5 * 16 + kk) * 64 + pp] = b4.y;
                gs[(6 * 16 + kk) * 64 + pp] = b4.z;
                gs[(7 * 16 + kk) * 64 + pp] = b4.w;
            } else {
                const float* a = addf + ((size_t)pid * 16 + kk) * 3;
                gs[(0 * 16 + kk) * 64 + pp] = a[0];
                gs[(1 * 16 + kk) * 64 + pp] = a[1];
                gs[(2 * 16 + kk) * 64 + pp] = a[2];
                gs[(3 * 16 + kk) * 64 + pp] = 0.f;
            }
        }
        __syncthreads();

        const int ncl = (gidx < 8) ? 4 : 2;
        for (int cl2 = 0; cl2 < ncl; ++cl2, ++cg) {
            const int buf = cg & 1;
            float* Pb = sm + OFF_PT + buf * TILE_FL;
            const uint32_t bufoff = (uint32_t)(buf * TILE_FL) * 4;

            // ---- P compute: 2 channels x 4 m over 16 k (regs) ----
            #pragma unroll
            for (int cl = 0; cl < 2; ++cl) {
                int gb = ((cl2 * 2 + cl) * 16) * 64 + p;
                unsigned long long a0 = 0, a1 = 0;
                #pragma unroll
                for (int k = 0; k < 16; ++k) {
                    float gv = gs[gb + k * 64];
                    unsigned long long g2 = pack2(gv, gv);
                    fma2(a0, g2, wn2[k][0]);
                    fma2(a1, g2, wn2[k][1]);
                }
                float v0, v1, v2, v3;
                unpack2(a0, v0, v1); unpack2(a1, v2, v3);
                uint32_t* dst = (uint32_t*)(Pb + p * TSTRIDE + cl * 16 + mq * 4);
                *(uint4*)dst = make_uint4(cvt_tf32(v0), cvt_tf32(v1),
                                          cvt_tf32(v2), cvt_tf32(v3));
            }
            __syncthreads();

            // ---- ldsm A + LDG B fragments + 32 HMMA per warp ----
            const float* bc = bq + (size_t)cg * 4096;
            #pragma unroll
            for (int ks = 0; ks < 4; ++ks) {
                uint32_t a0r[4], a1r[4];
                ldsm4(a0r, aBase + bufoff + ks * 32);
                ldsm4(a1r, aBase + bufoff + 16 * TSTRIDE * 4 + ks * 32);
                uint4 u0 = *(const uint4*)(bc + ks * 8);
                uint4 u1 = *(const uint4*)(bc + ks * 8 + 4);
                mma8(acc[0][0], a0r, u0.x, u0.y);
                mma8(acc[0][1], a0r, u0.z, u0.w);
                mma8(acc[1][0], a1r, u0.x, u0.y);
                mma8(acc[1][1], a1r, u0.z, u0.w);
                mma8(acc[0][2], a0r, u1.x, u1.y);
                mma8(acc[0][3], a0r, u1.z, u1.w);
                mma8(acc[1][2], a1r, u1.x, u1.y);
                mma8(acc[1][3], a1r, u1.z, u1.w);
            }
            // no trailing sync: P tiles double-buffered; the next chunk's sync
            // orders MMA(c) before the buffer is overwritten at chunk c+2.
        }
    }

    // ---- epilogue: bias + store (each warp 32p x 32o) ----
    #pragma unroll
    for (int mt = 0; mt < 2; ++mt) {
        int r = wm * 32 + mt * 16 + (l >> 2);
        #pragma unroll
        for (int nt = 0; nt < 4; ++nt) {
            int o  = wn4 * 32 + nt * 8 + 2 * (l & 3);
            float b0 = sm[OFF_BIAS + o], b1 = sm[OFF_BIAS + o + 1];
            int pid = base + r;
            *(float2*)(out + (size_t)pid * 128 + o) =
                make_float2(acc[mt][nt][0] + b0, acc[mt][nt][1] + b1);
            *(float2*)(out + (size_t)(pid + 8) * 128 + o) =
                make_float2(acc[mt][nt][2] + b0, acc[mt][nt][3] + b1);
        }
    }
}

extern "C" void kernel_launch(void* const* d_in, const int* in_sizes, int n_in,
                              void* d_out, int out_size) {
    const float* xin  = (const float*)d_in[0];
    const int*   nbr  = (const int*)d_in[1];
    const float* wng  = (const float*)d_in[2];
    const float* addf = (const float*)d_in[3];
    const float* W    = (const float*)d_in[4];
    const float* bias = (const float*)d_in[5];
    float*       out  = (float*)d_out;

    cudaFuncSetAttribute(pcl_kernel,
                         cudaFuncAttributeMaxDynamicSharedMemorySize, SMEM_BYTES);

    prep_kernel<<<NCHUNK, 128>>>(W);
    pcl_kernel<<<GRID, THREADS, SMEM_BYTES>>>(xin, nbr, wng, addf, bias, out);
}

// round 7
// speedup vs baseline: 1.8808x; 1.8808x over previous
#include <cuda_runtime.h>
#include <cstdint>

// ---------------------------------------------------------------------------
// PConvLinear via mma.sync tf32 (m16n8k8).
//   out[p,o] = bias[o] + sum_f P[p,f] * W[o,f]
//   P[p, c*16+m] = sum_{k<16} feat[p,k,c] * wn[p,k,m]
// Prep kernel: W -> tf32 B-fragments in gmem, COALESCED layout
//   Wfrag[cg][wn4][j=ks*2+np][lane][4]  (each warp-load = contiguous 512B).
// Main: 256 thr / 64 pts / 8 warps (2x4 grid, 32p x 32o), 2 CTAs/SM,
//       wn register-resident, 34 chunks of 32 f, 1 sync per chunk.
// ---------------------------------------------------------------------------

#define NPTS 120000
#define NB   60000
#define TPB  64
#define THREADS 256
#define GRID (NPTS / TPB)      // 1875 exactly
#define NCHUNK 34

#define TSTRIDE 36             // padded float stride of tf32 tiles
#define TILE_FL (64 * TSTRIDE) // 2304 floats per P-tile buffer

// smem layout (float offsets)
#define OFF_PT   0                    // 2 x 2304  P tf32 [p][f]
#define OFF_G    (2 * TILE_FL)        // 8192: feats [c*16+k][64p] / wn scratch
#define OFF_I    (2 * TILE_FL + 8192) // 1024 ints neighbor inds
#define OFF_BIAS (OFF_I + 1024)       // 128
#define SMEM_FLOATS (OFF_BIAS + 128)
#define SMEM_BYTES (SMEM_FLOATS * 4)  // 55,808 B -> 2 CTAs/SM

// wn staging: XOR-swizzled column to avoid 32-way STS conflicts
#define WNC(r, p) ((r) * 64 + ((p) ^ (((r) >> 2) & 31)))

// W fragments: [cg 34][wn4 4][j 8][lane 32][4]  = 34*4096 floats
__device__ float Wfrag[34 * 4 * 8 * 32 * 4];

__device__ __forceinline__ uint32_t smem_u32(const void* p) {
    uint32_t a;
    asm("{ .reg .u64 t; cvta.to.shared.u64 t, %1; cvt.u32.u64 %0, t; }"
        : "=r"(a) : "l"(p));
    return a;
}
__device__ __forceinline__ uint32_t cvt_tf32(float f) {
    uint32_t r; asm("cvt.rna.tf32.f32 %0, %1;" : "=r"(r) : "f"(f)); return r;
}
__device__ __forceinline__ unsigned long long pack2(float lo, float hi) {
    unsigned long long r;
    asm("mov.b64 %0, {%1, %2};" : "=l"(r) : "f"(lo), "f"(hi));
    return r;
}
__device__ __forceinline__ void unpack2(unsigned long long v, float& lo, float& hi) {
    asm("mov.b64 {%0, %1}, %2;" : "=f"(lo), "=f"(hi) : "l"(v));
}
__device__ __forceinline__ void fma2(unsigned long long& d,
                                     unsigned long long a, unsigned long long b) {
    asm("fma.rn.f32x2 %0, %1, %2, %0;" : "+l"(d) : "l"(a), "l"(b));
}
__device__ __forceinline__ void ldsm4(uint32_t r[4], uint32_t addr) {
    asm volatile("ldmatrix.sync.aligned.m8n8.x4.shared.b16 {%0,%1,%2,%3}, [%4];"
                 : "=r"(r[0]), "=r"(r[1]), "=r"(r[2]), "=r"(r[3]) : "r"(addr));
}
__device__ __forceinline__ void mma8(float c[4], const uint32_t a[4],
                                     uint32_t b0, uint32_t b1) {
    asm volatile(
        "mma.sync.aligned.m16n8k8.row.col.f32.tf32.tf32.f32 "
        "{%0,%1,%2,%3}, {%4,%5,%6,%7}, {%8,%9}, {%0,%1,%2,%3};"
        : "+f"(c[0]), "+f"(c[1]), "+f"(c[2]), "+f"(c[3])
        : "r"(a[0]), "r"(a[1]), "r"(a[2]), "r"(a[3]), "r"(b0), "r"(b1));
}

// ---- prep: stage W chunk, ldmatrix once, store coalesced fragments ----
extern "C" __global__ void __launch_bounds__(128, 1)
prep_kernel(const float* __restrict__ W) {
    __shared__ float ws[128 * TSTRIDE];
    const int cg = blockIdx.x;
    const int t  = threadIdx.x;
    const int l  = t & 31;
    const int w  = t >> 5;               // wn4 this warp produces
    const int f0 = cg * 32;

    #pragma unroll
    for (int j = 0; j < 8; ++j) {
        int f = f0 + j * 4;
        float4 v = (f < 1072)
            ? *(const float4*)(W + (size_t)t * 1072 + f)
            : make_float4(0.f, 0.f, 0.f, 0.f);
        *(uint4*)(ws + t * TSTRIDE + j * 4) =
            make_uint4(cvt_tf32(v.x), cvt_tf32(v.y), cvt_tf32(v.z), cvt_tf32(v.w));
    }
    __syncthreads();

    const uint32_t bBase = smem_u32(ws) +
        (uint32_t)((w * 32 + (l & 7) + ((l & 16) ? 8 : 0)) * TSTRIDE
                   + ((l & 8) ? 4 : 0)) * 4;
    float* dst = Wfrag + ((size_t)cg * 4 + w) * 1024;   // + j*128 + l*4
    #pragma unroll
    for (int ks = 0; ks < 4; ++ks)
        #pragma unroll
        for (int np = 0; np < 2; ++np) {
            uint32_t b[4];
            ldsm4(b, bBase + np * 16 * TSTRIDE * 4 + ks * 32);
            *(uint4*)(dst + (ks * 2 + np) * 128 + l * 4) =
                make_uint4(b[0], b[1], b[2], b[3]);
        }
}

// ---- main ----
extern "C" __global__ void __launch_bounds__(THREADS, 2)
pcl_kernel(const float* __restrict__ xin,   // [2,60000,64]
           const int*   __restrict__ nbr,   // [2,60000,16]
           const float* __restrict__ wng,   // [2,60000,16,16]
           const float* __restrict__ addf,  // [2,60000,16,3]
           const float* __restrict__ bias,  // [128]
           float*       __restrict__ out)   // [2,60000,128]
{
    extern __shared__ __align__(16) float sm[];
    float* gs   = sm + OFF_G;
    int*   inds = (int*)(sm + OFF_I);

    const uint32_t smb = smem_u32(sm);
    const int t    = threadIdx.x;
    const int wid  = t >> 5;
    const int l    = t & 31;
    const int base = blockIdx.x * TPB;
    const int p    = t & 63;           // P-compute: point
    const int mq   = t >> 6;           // P-compute: m-quad (4 m)

    // MMA roles: warp grid 2(m) x 4(n); each warp 32p x 32o
    const int wm   = wid & 1;
    const int wn4  = wid >> 1;
    const uint32_t aBase = smb + (uint32_t)(OFF_PT + (wm * 32 + (l & 15)) * TSTRIDE
                                            + ((l & 16) ? 4 : 0)) * 4;
    // coalesced fragment pointer: + cg*4096 per chunk, + j*128 per load
    const float* bq = Wfrag + (size_t)wn4 * 1024 + l * 4;

    if (t < 128) sm[OFF_BIAS + t] = bias[t];

    // ---- neighbor indices: 64 pts x 16 ----
    {
        int pt = base + (t >> 2);
        ((int4*)inds)[t] = *(const int4*)(nbr + (size_t)pt * 16 + (size_t)(t & 3) * 4);
    }

    // ---- stage wn (two halves through gs, XOR-swizzled), into registers ----
    unsigned long long wn2[16][2];
    #pragma unroll
    for (int h = 0; h < 2; ++h) {
        __syncthreads();
        #pragma unroll
        for (int rep = 0; rep < 8; ++rep) {
            int lin = rep * 1024 + t * 4;       // 0..8191
            int pp  = lin >> 7;                 // 0..63
            int r   = lin & 127;                // k*16+m, multiple of 4
            int pid = base + pp;
            float4 v = *(const float4*)(wng + (size_t)pid * 256 + h * 128 + r);
            gs[WNC(r + 0, pp)] = v.x;
            gs[WNC(r + 1, pp)] = v.y;
            gs[WNC(r + 2, pp)] = v.z;
            gs[WNC(r + 3, pp)] = v.w;
        }
        __syncthreads();
        #pragma unroll
        for (int k = 0; k < 8; ++k)
            #pragma unroll
            for (int j2 = 0; j2 < 2; ++j2) {
                int r0 = k * 16 + mq * 4 + j2 * 2;
                float lo = gs[WNC(r0 + 0, p)];
                float hi = gs[WNC(r0 + 1, p)];
                wn2[h * 8 + k][j2] = pack2(lo, hi);
            }
    }

    float acc[2][4][4];
    #pragma unroll
    for (int i = 0; i < 2; ++i)
        #pragma unroll
        for (int j = 0; j < 4; ++j)
            #pragma unroll
            for (int q = 0; q < 4; ++q) acc[i][j][q] = 0.f;

    int cg = 0;
    for (int gidx = 0; gidx < 9; ++gidx) {
        // ---- stage gathered feats gs[(c*16+k)][p]: 8 ch x 16 k x 64 p ----
        __syncthreads();
        #pragma unroll
        for (int rep = 0; rep < 4; ++rep) {
            int v  = rep * 256 + t;             // 0..1023
            int pp = v & 63, kk = v >> 6;       // kk 0..15
            int pid = base + pp;
            if (gidx < 8) {
                int nb   = inds[pp * 16 + kk];
                int brow = (pid >= NB) ? NB : 0;
                const float4* src =
                    (const float4*)(xin + ((size_t)brow + nb) * 64 + gidx * 8);
                float4 a = src[0], b4 = src[1];
                gs[(0 * 16 + kk) * 64 + pp] = a.x;
                gs[(1 * 16 + kk) * 64 + pp] = a.y;
                gs[(2 * 16 + kk) * 64 + pp] = a.z;
                gs[(3 * 16 + kk) * 64 + pp] = a.w;
                gs[(4 * 16 + kk) * 64 + pp] = b4.x;
                gs[(5 * 16 + kk) * 64 + pp] = b4.y;
                gs[(6 * 16 + kk) * 64 + pp] = b4.z;
                gs[(7 * 16 + kk) * 64 + pp] = b4.w;
            } else {
                const float* a = addf + ((size_t)pid * 16 + kk) * 3;
                gs[(0 * 16 + kk) * 64 + pp] = a[0];
                gs[(1 * 16 + kk) * 64 + pp] = a[1];
                gs[(2 * 16 + kk) * 64 + pp] = a[2];
                gs[(3 * 16 + kk) * 64 + pp] = 0.f;
            }
        }
        __syncthreads();

        const int ncl = (gidx < 8) ? 4 : 2;
        for (int cl2 = 0; cl2 < ncl; ++cl2, ++cg) {
            const int buf = cg & 1;
            float* Pb = sm + OFF_PT + buf * TILE_FL;
            const uint32_t bufoff = (uint32_t)(buf * TILE_FL) * 4;

            // ---- P compute: 2 channels x 4 m over 16 k (regs) ----
            #pragma unroll
            for (int cl = 0; cl < 2; ++cl) {
                int gb = ((cl2 * 2 + cl) * 16) * 64 + p;
                unsigned long long a0 = 0, a1 = 0;
                #pragma unroll
                for (int k = 0; k < 16; ++k) {
                    float gv = gs[gb + k * 64];
                    unsigned long long g2 = pack2(gv, gv);
                    fma2(a0, g2, wn2[k][0]);
                    fma2(a1, g2, wn2[k][1]);
                }
                float v0, v1, v2, v3;
                unpack2(a0, v0, v1); unpack2(a1, v2, v3);
                uint32_t* dst = (uint32_t*)(Pb + p * TSTRIDE + cl * 16 + mq * 4);
                *(uint4*)dst = make_uint4(cvt_tf32(v0), cvt_tf32(v1),
                                          cvt_tf32(v2), cvt_tf32(v3));
            }

            // ---- B fragments: 8 coalesced LDG.128 (hide L2 under sync+ldsm) ----
            const float* bc = bq + (size_t)cg * 4096;
            uint4 u[8];
            #pragma unroll
            for (int j = 0; j < 8; ++j)
                u[j] = *(const uint4*)(bc + j * 128);

            __syncthreads();

            // ---- ldsm A + 32 HMMA per warp ----
            #pragma unroll
            for (int ks = 0; ks < 4; ++ks) {
                uint32_t a0r[4], a1r[4];
                ldsm4(a0r, aBase + bufoff + ks * 32);
                ldsm4(a1r, aBase + bufoff + 16 * TSTRIDE * 4 + ks * 32);
                mma8(acc[0][0], a0r, u[ks * 2].x, u[ks * 2].y);
                mma8(acc[0][1], a0r, u[ks * 2].z, u[ks * 2].w);
                mma8(acc[1][0], a1r, u[ks * 2].x, u[ks * 2].y);
                mma8(acc[1][1], a1r, u[ks * 2].z, u[ks * 2].w);
                mma8(acc[0][2], a0r, u[ks * 2 + 1].x, u[ks * 2 + 1].y);
                mma8(acc[0][3], a0r, u[ks * 2 + 1].z, u[ks * 2 + 1].w);
                mma8(acc[1][2], a1r, u[ks * 2 + 1].x, u[ks * 2 + 1].y);
                mma8(acc[1][3], a1r, u[ks * 2 + 1].z, u[ks * 2 + 1].w);
            }
            // no trailing sync: P tiles double-buffered; the next chunk's sync
            // orders MMA(c) before the buffer is overwritten at chunk c+2.
        }
    }

    // ---- epilogue: bias + store (each warp 32p x 32o) ----
    #pragma unroll
    for (int mt = 0; mt < 2; ++mt) {
        int r = wm * 32 + mt * 16 + (l >> 2);
        #pragma unroll
        for (int nt = 0; nt < 4; ++nt) {
            int o  = wn4 * 32 + nt * 8 + 2 * (l & 3);
            float b0 = sm[OFF_BIAS + o], b1 = sm[OFF_BIAS + o + 1];
            int pid = base + r;
            *(float2*)(out + (size_t)pid * 128 + o) =
                make_float2(acc[mt][nt][0] + b0, acc[mt][nt][1] + b1);
            *(float2*)(out + (size_t)(pid + 8) * 128 + o) =
                make_float2(acc[mt][nt][2] + b0, acc[mt][nt][3] + b1);
        }
    }
}

extern "C" void kernel_launch(void* const* d_in, const int* in_sizes, int n_in,
                              void* d_out, int out_size) {
    const float* xin  = (const float*)d_in[0];
    const int*   nbr  = (const int*)d_in[1];
    const float* wng  = (const float*)d_in[2];
    const float* addf = (const float*)d_in[3];
    const float* W    = (const float*)d_in[4];
    const float* bias = (const float*)d_in[5];
    float*       out  = (float*)d_out;

    cudaFuncSetAttribute(pcl_kernel,
                         cudaFuncAttributeMaxDynamicSharedMemorySize, SMEM_BYTES);

    prep_kernel<<<NCHUNK, 128>>>(W);
    pcl_kernel<<<GRID, THREADS, SMEM_BYTES>>>(xin, nbr, wng, addf, bias, out);
}

// round 8
// speedup vs baseline: 2.3487x; 1.2488x over previous
#include <cuda_runtime.h>
#include <cstdint>

// ---------------------------------------------------------------------------
// PConvLinear via mma.sync tf32 (m16n8k8).
//   out[p,o] = bias[o] + sum_f P[p,f] * W[o,f]
//   P[p, c*16+m] = sum_{k<16} feat[p,k,c] * wn[p,k,m]
// Prep kernel: W -> tf32 B-fragments in gmem (coalesced layout).
// Main: 256 thr / 64 pts / 8 warps (2x4, 32p x 32o), 2 CTAs/SM.
// Gather staged in 16-channel mega-groups: 4 lanes cooperate per (pt,k)
// visit (one 128B line / visit), XOR-swizzled smem, 34 chunks of 32 f.
// ---------------------------------------------------------------------------

#define NPTS 120000
#define NB   60000
#define TPB  64
#define THREADS 256
#define GRID (NPTS / TPB)      // 1875 exactly
#define NCHUNK 34

#define TSTRIDE 36             // padded float stride of tf32 P tiles
#define TILE_FL (64 * TSTRIDE) // 2304 floats per P-tile buffer

// smem layout (float offsets)
#define OFF_PT   0                      // 2 x 2304  P tf32 [p][f]
#define OFF_G    (2 * TILE_FL)          // 16384: feats [c16*16+k][64p] (swz)
#define OFF_I    (2 * TILE_FL + 16384)  // 1024 ints neighbor inds
#define OFF_BIAS (OFF_I + 1024)         // 128
#define SMEM_FLOATS (OFF_BIAS + 128)
#define SMEM_BYTES (SMEM_FLOATS * 4)    // 88,576 B -> 2 CTAs/SM

// wn prologue staging: XOR-swizzled column (32-way STS conflict fix)
#define WNC(r, p) ((r) * 64 + ((p) ^ (((r) >> 2) & 31)))

// W fragments: [cg 34][wn4 4][j 8][lane 32][4]
__device__ float Wfrag[34 * 4 * 8 * 32 * 4];

__device__ __forceinline__ uint32_t smem_u32(const void* p) {
    uint32_t a;
    asm("{ .reg .u64 t; cvta.to.shared.u64 t, %1; cvt.u32.u64 %0, t; }"
        : "=r"(a) : "l"(p));
    return a;
}
__device__ __forceinline__ uint32_t cvt_tf32(float f) {
    uint32_t r; asm("cvt.rna.tf32.f32 %0, %1;" : "=r"(r) : "f"(f)); return r;
}
__device__ __forceinline__ unsigned long long pack2(float lo, float hi) {
    unsigned long long r;
    asm("mov.b64 %0, {%1, %2};" : "=l"(r) : "f"(lo), "f"(hi));
    return r;
}
__device__ __forceinline__ void unpack2(unsigned long long v, float& lo, float& hi) {
    asm("mov.b64 {%0, %1}, %2;" : "=f"(lo), "=f"(hi) : "l"(v));
}
__device__ __forceinline__ void fma2(unsigned long long& d,
                                     unsigned long long a, unsigned long long b) {
    asm("fma.rn.f32x2 %0, %1, %2, %0;" : "+l"(d) : "l"(a), "l"(b));
}
__device__ __forceinline__ void ldsm4(uint32_t r[4], uint32_t addr) {
    asm volatile("ldmatrix.sync.aligned.m8n8.x4.shared.b16 {%0,%1,%2,%3}, [%4];"
                 : "=r"(r[0]), "=r"(r[1]), "=r"(r[2]), "=r"(r[3]) : "r"(addr));
}
__device__ __forceinline__ void mma8(float c[4], const uint32_t a[4],
                                     uint32_t b0, uint32_t b1) {
    asm volatile(
        "mma.sync.aligned.m16n8k8.row.col.f32.tf32.tf32.f32 "
        "{%0,%1,%2,%3}, {%4,%5,%6,%7}, {%8,%9}, {%0,%1,%2,%3};"
        : "+f"(c[0]), "+f"(c[1]), "+f"(c[2]), "+f"(c[3])
        : "r"(a[0]), "r"(a[1]), "r"(a[2]), "r"(a[3]), "r"(b0), "r"(b1));
}

// ---- prep: stage W chunk, ldmatrix once, store coalesced fragments ----
extern "C" __global__ void __launch_bounds__(128, 1)
prep_kernel(const float* __restrict__ W) {
    __shared__ float ws[128 * TSTRIDE];
    const int cg = blockIdx.x;
    const int t  = threadIdx.x;
    const int l  = t & 31;
    const int w  = t >> 5;
    const int f0 = cg * 32;

    #pragma unroll
    for (int j = 0; j < 8; ++j) {
        int f = f0 + j * 4;
        float4 v = (f < 1072)
            ? *(const float4*)(W + (size_t)t * 1072 + f)
            : make_float4(0.f, 0.f, 0.f, 0.f);
        *(uint4*)(ws + t * TSTRIDE + j * 4) =
            make_uint4(cvt_tf32(v.x), cvt_tf32(v.y), cvt_tf32(v.z), cvt_tf32(v.w));
    }
    __syncthreads();

    const uint32_t bBase = smem_u32(ws) +
        (uint32_t)((w * 32 + (l & 7) + ((l & 16) ? 8 : 0)) * TSTRIDE
                   + ((l & 8) ? 4 : 0)) * 4;
    float* dst = Wfrag + ((size_t)cg * 4 + w) * 1024;
    #pragma unroll
    for (int ks = 0; ks < 4; ++ks)
        #pragma unroll
        for (int np = 0; np < 2; ++np) {
            uint32_t b[4];
            ldsm4(b, bBase + np * 16 * TSTRIDE * 4 + ks * 32);
            *(uint4*)(dst + (ks * 2 + np) * 128 + l * 4) =
                make_uint4(b[0], b[1], b[2], b[3]);
        }
}

// ---- main ----
extern "C" __global__ void __launch_bounds__(THREADS, 2)
pcl_kernel(const float* __restrict__ xin,   // [2,60000,64]
           const int*   __restrict__ nbr,   // [2,60000,16]
           const float* __restrict__ wng,   // [2,60000,16,16]
           const float* __restrict__ addf,  // [2,60000,16,3]
           const float* __restrict__ bias,  // [128]
           float*       __restrict__ out)   // [2,60000,128]
{
    extern __shared__ __align__(16) float sm[];
    float* gs   = sm + OFF_G;
    int*   inds = (int*)(sm + OFF_I);

    const uint32_t smb = smem_u32(sm);
    const int t    = threadIdx.x;
    const int wid  = t >> 5;
    const int l    = t & 31;
    const int base = blockIdx.x * TPB;
    const int p    = t & 63;           // P-compute: point
    const int mq   = t >> 6;           // P-compute: m-quad (4 m)

    // MMA roles: warp grid 2(m) x 4(n); each warp 32p x 32o
    const int wm   = wid & 1;
    const int wn4  = wid >> 1;
    const uint32_t aBase = smb + (uint32_t)(OFF_PT + (wm * 32 + (l & 15)) * TSTRIDE
                                            + ((l & 16) ? 4 : 0)) * 4;
    const float* bq = Wfrag + (size_t)wn4 * 1024 + l * 4;

    if (t < 128) sm[OFF_BIAS + t] = bias[t];

    // ---- neighbor indices: 64 pts x 16 ----
    {
        int pt = base + (t >> 2);
        ((int4*)inds)[t] = *(const int4*)(nbr + (size_t)pt * 16 + (size_t)(t & 3) * 4);
    }

    // ---- stage wn (two halves through gs, XOR-swizzled), into registers ----
    unsigned long long wn2[16][2];
    #pragma unroll
    for (int h = 0; h < 2; ++h) {
        __syncthreads();
        #pragma unroll
        for (int rep = 0; rep < 8; ++rep) {
            int lin = rep * 1024 + t * 4;
            int pp  = lin >> 7;
            int r   = lin & 127;
            int pid = base + pp;
            float4 v = *(const float4*)(wng + (size_t)pid * 256 + h * 128 + r);
            gs[WNC(r + 0, pp)] = v.x;
            gs[WNC(r + 1, pp)] = v.y;
            gs[WNC(r + 2, pp)] = v.z;
            gs[WNC(r + 3, pp)] = v.w;
        }
        __syncthreads();
        #pragma unroll
        for (int k = 0; k < 8; ++k)
            #pragma unroll
            for (int j2 = 0; j2 < 2; ++j2) {
                int r0 = k * 16 + mq * 4 + j2 * 2;
                float lo = gs[WNC(r0 + 0, p)];
                float hi = gs[WNC(r0 + 1, p)];
                wn2[h * 8 + k][j2] = pack2(lo, hi);
            }
    }

    float acc[2][4][4];
    #pragma unroll
    for (int i = 0; i < 2; ++i)
        #pragma unroll
        for (int j = 0; j < 4; ++j)
            #pragma unroll
            for (int q = 0; q < 4; ++q) acc[i][j][q] = 0.f;

    int cg = 0;
    for (int mega = 0; mega < 5; ++mega) {
        // ---- mega gather: 16 channels (or addf), XOR-swizzled gs ----
        __syncthreads();
        if (mega < 4) {
            // 4 lanes cooperate per (pt,k) visit: one 128B line per visit.
            // gs[(c_l*16+k)*64 + (pp ^ 8*(c_l>>2))], c_l = 4w+ci.
            #pragma unroll
            for (int rep = 0; rep < 16; ++rep) {
                int idx   = rep * 256 + t;
                int w     = idx & 3;                 // channel quad
                int visit = idx >> 2;                // 0..1023
                int pp    = visit & 63;
                int kk    = visit >> 6;
                int pid   = base + pp;
                int nb    = inds[pp * 16 + kk];
                int brow  = (pid >= NB) ? NB : 0;
                float4 v  = *(const float4*)(xin + (size_t)(brow + nb) * 64
                                             + mega * 16 + w * 4);
                int col  = pp ^ (w * 8);
                int rowb = (w * 64 + kk) * 64 + col; // row = 64w + 16ci + kk
                gs[rowb + 0 * 16 * 64] = v.x;
                gs[rowb + 1 * 16 * 64] = v.y;
                gs[rowb + 2 * 16 * 64] = v.z;
                gs[rowb + 3 * 16 * 64] = v.w;
            }
        } else {
            // addf: 3 channels into c_l 0..2 (+zero), swizzle s=0 for c_l<4
            #pragma unroll
            for (int rep = 0; rep < 4; ++rep) {
                int v  = rep * 256 + t;
                int pp = v & 63, kk = v >> 6;
                int pid = base + pp;
                const float* a = addf + ((size_t)pid * 16 + kk) * 3;
                gs[(0 * 16 + kk) * 64 + pp] = a[0];
                gs[(1 * 16 + kk) * 64 + pp] = a[1];
                gs[(2 * 16 + kk) * 64 + pp] = a[2];
                gs[(3 * 16 + kk) * 64 + pp] = 0.f;
            }
        }
        __syncthreads();

        const int nch = (mega < 4) ? 8 : 2;
        for (int i = 0; i < nch; ++i, ++cg) {
            const int buf = cg & 1;
            float* Pb = sm + OFF_PT + buf * TILE_FL;
            const uint32_t bufoff = (uint32_t)(buf * TILE_FL) * 4;

            // ---- P compute: 2 channels x 4 m over 16 k (regs) ----
            #pragma unroll
            for (int cl = 0; cl < 2; ++cl) {
                int c_l = i * 2 + cl;
                int gb  = (c_l * 16) * 64 + (p ^ ((c_l >> 2) * 8));
                unsigned long long a0 = 0, a1 = 0;
                #pragma unroll
                for (int k = 0; k < 16; ++k) {
                    float gv = gs[gb + k * 64];
                    unsigned long long g2 = pack2(gv, gv);
                    fma2(a0, g2, wn2[k][0]);
                    fma2(a1, g2, wn2[k][1]);
                }
                float v0, v1, v2, v3;
                unpack2(a0, v0, v1); unpack2(a1, v2, v3);
                uint32_t* dst = (uint32_t*)(Pb + p * TSTRIDE + cl * 16 + mq * 4);
                *(uint4*)dst = make_uint4(cvt_tf32(v0), cvt_tf32(v1),
                                          cvt_tf32(v2), cvt_tf32(v3));
            }

            // ---- B fragments: 8 coalesced LDG.128 (hide under sync+ldsm) ----
            const float* bc = bq + (size_t)cg * 4096;
            uint4 u[8];
            #pragma unroll
            for (int j = 0; j < 8; ++j)
                u[j] = *(const uint4*)(bc + j * 128);

            __syncthreads();

            // ---- ldsm A + 32 HMMA per warp ----
            #pragma unroll
            for (int ks = 0; ks < 4; ++ks) {
                uint32_t a0r[4], a1r[4];
                ldsm4(a0r, aBase + bufoff + ks * 32);
                ldsm4(a1r, aBase + bufoff + 16 * TSTRIDE * 4 + ks * 32);
                mma8(acc[0][0], a0r, u[ks * 2].x, u[ks * 2].y);
                mma8(acc[0][1], a0r, u[ks * 2].z, u[ks * 2].w);
                mma8(acc[1][0], a1r, u[ks * 2].x, u[ks * 2].y);
                mma8(acc[1][1], a1r, u[ks * 2].z, u[ks * 2].w);
                mma8(acc[0][2], a0r, u[ks * 2 + 1].x, u[ks * 2 + 1].y);
                mma8(acc[0][3], a0r, u[ks * 2 + 1].z, u[ks * 2 + 1].w);
                mma8(acc[1][2], a1r, u[ks * 2 + 1].x, u[ks * 2 + 1].y);
                mma8(acc[1][3], a1r, u[ks * 2 + 1].z, u[ks * 2 + 1].w);
            }
            // no trailing sync: P tiles double-buffered; the next chunk's sync
            // orders MMA(c) before the buffer is overwritten at chunk c+2.
        }
    }

    // ---- epilogue: bias + store (each warp 32p x 32o) ----
    #pragma unroll
    for (int mt = 0; mt < 2; ++mt) {
        int r = wm * 32 + mt * 16 + (l >> 2);
        #pragma unroll
        for (int nt = 0; nt < 4; ++nt) {
            int o  = wn4 * 32 + nt * 8 + 2 * (l & 3);
            float b0 = sm[OFF_BIAS + o], b1 = sm[OFF_BIAS + o + 1];
            int pid = base + r;
            *(float2*)(out + (size_t)pid * 128 + o) =
                make_float2(acc[mt][nt][0] + b0, acc[mt][nt][1] + b1);
            *(float2*)(out + (size_t)(pid + 8) * 128 + o) =
                make_float2(acc[mt][nt][2] + b0, acc[mt][nt][3] + b1);
        }
    }
}

extern "C" void kernel_launch(void* const* d_in, const int* in_sizes, int n_in,
                              void* d_out, int out_size) {
    const float* xin  = (const float*)d_in[0];
    const int*   nbr  = (const int*)d_in[1];
    const float* wng  = (const float*)d_in[2];
    const float* addf = (const float*)d_in[3];
    const float* W    = (const float*)d_in[4];
    const float* bias = (const float*)d_in[5];
    float*       out  = (float*)d_out;

    cudaFuncSetAttribute(pcl_kernel,
                         cudaFuncAttributeMaxDynamicSharedMemorySize, SMEM_BYTES);

    prep_kernel<<<NCHUNK, 128>>>(W);
    pcl_kernel<<<GRID, THREADS, SMEM_BYTES>>>(xin, nbr, wng, addf, bias, out);
}

// round 9
// speedup vs baseline: 3.2571x; 1.3867x over previous
#include <cuda_runtime.h>
#include <cstdint>

// ---------------------------------------------------------------------------
// PConvLinear via mma.sync fp16 (m16n8k16), fp32 accumulate.
//   out[p,o] = bias[o] + sum_f P[p,f] * W[o,f]
//   P[p, c*16+m] = sum_{k<16} feat[p,k,c] * wn[p,k,m]
// fp16 has the same 10-bit mantissa as tf32 -> same accuracy, half the bytes.
// Prep kernel: W -> fp16 B-fragments (analytic layout, coalesced).
// Main: 256 thr / 64 pts / 8 warps (2x4, 32p x 32o), 2 CTAs/SM,
// mega-gather (R8), XOR-swizzled fp16 P tiles, 34 chunks of 32 f.
// ---------------------------------------------------------------------------

#define NPTS 120000
#define NB   60000
#define TPB  64
#define THREADS 256
#define GRID (NPTS / TPB)      // 1875
#define NCHUNK 34

#define PROWB 80               // P-tile row stride in bytes (fp16 32 f = 64B + pad)
#define PTILEB (64 * PROWB)    // 5120 B per buffer

// smem layout (float offsets)
#define OFF_G    2560                  // after 2 x 5120B P tiles
#define OFF_I    (OFF_G + 16384)       // 1024 ints neighbor inds
#define OFF_BIAS (OFF_I + 1024)        // 128
#define SMEM_FLOATS (OFF_BIAS + 128)
#define SMEM_BYTES (SMEM_FLOATS * 4)   // 80,384 B -> 2 CTAs/SM

// wn prologue staging: XOR-swizzled column (32-way STS conflict fix)
#define WNC(r, p) ((r) * 64 + ((p) ^ (((r) >> 2) & 31)))

// W fragments: [cg 34][wn4 4][q 4][lane 32][4] uint32
__device__ uint32_t Wfrag[34 * 2048];

__device__ __forceinline__ uint32_t smem_u32(const void* p) {
    uint32_t a;
    asm("{ .reg .u64 t; cvta.to.shared.u64 t, %1; cvt.u32.u64 %0, t; }"
        : "=r"(a) : "l"(p));
    return a;
}
__device__ __forceinline__ uint32_t pack_f16x2(float lo, float hi) {
    uint32_t r;
    asm("cvt.rn.f16x2.f32 %0, %1, %2;" : "=r"(r) : "f"(hi), "f"(lo));
    return r;
}
__device__ __forceinline__ unsigned long long pack2(float lo, float hi) {
    unsigned long long r;
    asm("mov.b64 %0, {%1, %2};" : "=l"(r) : "f"(lo), "f"(hi));
    return r;
}
__device__ __forceinline__ void unpack2(unsigned long long v, float& lo, float& hi) {
    asm("mov.b64 {%0, %1}, %2;" : "=f"(lo), "=f"(hi) : "l"(v));
}
__device__ __forceinline__ void fma2(unsigned long long& d,
                                     unsigned long long a, unsigned long long b) {
    asm("fma.rn.f32x2 %0, %1, %2, %0;" : "+l"(d) : "l"(a), "l"(b));
}
__device__ __forceinline__ void ldsm4(uint32_t r[4], uint32_t addr) {
    asm volatile("ldmatrix.sync.aligned.m8n8.x4.shared.b16 {%0,%1,%2,%3}, [%4];"
                 : "=r"(r[0]), "=r"(r[1]), "=r"(r[2]), "=r"(r[3]) : "r"(addr));
}
__device__ __forceinline__ void mma16(float c[4], const uint32_t a[4],
                                      uint32_t b0, uint32_t b1) {
    asm volatile(
        "mma.sync.aligned.m16n8k16.row.col.f32.f16.f16.f32 "
        "{%0,%1,%2,%3}, {%4,%5,%6,%7}, {%8,%9}, {%0,%1,%2,%3};"
        : "+f"(c[0]), "+f"(c[1]), "+f"(c[2]), "+f"(c[3])
        : "r"(a[0]), "r"(a[1]), "r"(a[2]), "r"(a[3]), "r"(b0), "r"(b1));
}

// ---- prep: analytic fp16 B fragments ----
// mma m16n8k16 B frag (col-major B[k][n] = W[o=n][f=k]):
//   b0 = {W[o][f0+2c], W[o][f0+2c+1]}, b1 = same at f0+2c+8, c = l%4, o = n0+l/4
extern "C" __global__ void __launch_bounds__(128, 1)
prep_kernel(const float* __restrict__ W) {
    const int t  = threadIdx.x;
    const int l  = t & 31;
    const int w  = t >> 5;
    const int cg = blockIdx.x;
    const int ob = w * 32 + (l >> 2);
    const int c2 = (l & 3) * 2;

    #pragma unroll
    for (int ks = 0; ks < 2; ++ks)
        #pragma unroll
        for (int nth = 0; nth < 2; ++nth) {
            uint32_t r[4];
            #pragma unroll
            for (int h = 0; h < 2; ++h) {
                int o = ob + (nth * 2 + h) * 8;
                int f = cg * 32 + ks * 16 + c2;
                float a0 = 0.f, a1 = 0.f, b0 = 0.f, b1 = 0.f;
                if (f < 1072) {
                    float2 v = *(const float2*)(W + (size_t)o * 1072 + f);
                    a0 = v.x; a1 = v.y;
                }
                if (f + 8 < 1072) {
                    float2 v = *(const float2*)(W + (size_t)o * 1072 + f + 8);
                    b0 = v.x; b1 = v.y;
                }
                r[h * 2 + 0] = pack_f16x2(a0, a1);
                r[h * 2 + 1] = pack_f16x2(b0, b1);
            }
            *(uint4*)(Wfrag + cg * 2048 + w * 512 + (ks * 2 + nth) * 128 + l * 4) =
                make_uint4(r[0], r[1], r[2], r[3]);
        }
}

// ---- main ----
extern "C" __global__ void __launch_bounds__(THREADS, 2)
pcl_kernel(const float* __restrict__ xin,   // [2,60000,64]
           const int*   __restrict__ nbr,   // [2,60000,16]
           const float* __restrict__ wng,   // [2,60000,16,16]
           const float* __restrict__ addf,  // [2,60000,16,3]
           const float* __restrict__ bias,  // [128]
           float*       __restrict__ out)   // [2,60000,128]
{
    extern __shared__ __align__(16) float sm[];
    float* gs   = sm + OFF_G;
    int*   inds = (int*)(sm + OFF_I);
    char*  Pbase = (char*)sm;

    const uint32_t smb = smem_u32(sm);
    const int t    = threadIdx.x;
    const int wid  = t >> 5;
    const int l    = t & 31;
    const int base = blockIdx.x * TPB;
    const int p    = t & 63;           // P-compute: point
    const int mq   = t >> 6;           // P-compute: m-quad (4 m)

    // MMA roles: warp grid 2(m) x 4(n); each warp 32p x 32o
    const int wm   = wid & 1;
    const int wn4  = wid >> 1;
    // ldsm A addressing (XOR-swizzled fp16 P tile)
    const int arow_l = l & 15;                  // + wm*32 + mt*16
    const int ahi16  = ((l >> 4) & 1) * 16;
    const uint32_t* bq = Wfrag + wn4 * 512 + l * 4;

    if (t < 128) sm[OFF_BIAS + t] = bias[t];

    // ---- neighbor indices: 64 pts x 16 ----
    {
        int pt = base + (t >> 2);
        ((int4*)inds)[t] = *(const int4*)(nbr + (size_t)pt * 16 + (size_t)(t & 3) * 4);
    }

    // ---- stage wn (two halves through gs, XOR-swizzled), into registers ----
    unsigned long long wn2[16][2];
    #pragma unroll
    for (int h = 0; h < 2; ++h) {
        __syncthreads();
        #pragma unroll
        for (int rep = 0; rep < 8; ++rep) {
            int lin = rep * 1024 + t * 4;
            int pp  = lin >> 7;
            int r   = lin & 127;
            int pid = base + pp;
            float4 v = *(const float4*)(wng + (size_t)pid * 256 + h * 128 + r);
            gs[WNC(r + 0, pp)] = v.x;
            gs[WNC(r + 1, pp)] = v.y;
            gs[WNC(r + 2, pp)] = v.z;
            gs[WNC(r + 3, pp)] = v.w;
        }
        __syncthreads();
        #pragma unroll
        for (int k = 0; k < 8; ++k)
            #pragma unroll
            for (int j2 = 0; j2 < 2; ++j2) {
                int r0 = k * 16 + mq * 4 + j2 * 2;
                float lo = gs[WNC(r0 + 0, p)];
                float hi = gs[WNC(r0 + 1, p)];
                wn2[h * 8 + k][j2] = pack2(lo, hi);
            }
    }

    float acc[2][4][4];
    #pragma unroll
    for (int i = 0; i < 2; ++i)
        #pragma unroll
        for (int j = 0; j < 4; ++j)
            #pragma unroll
            for (int q = 0; q < 4; ++q) acc[i][j][q] = 0.f;

    // P STS address (fixed per thread): row p, col XOR-swizzled
    const uint32_t pXor = ((uint32_t)(p >> 3) & 3) << 4;

    int cg = 0;
    for (int mega = 0; mega < 5; ++mega) {
        // ---- mega gather: 16 channels (or addf), XOR-swizzled gs ----
        __syncthreads();
        if (mega < 4) {
            #pragma unroll
            for (int rep = 0; rep < 16; ++rep) {
                int idx   = rep * 256 + t;
                int w     = idx & 3;
                int visit = idx >> 2;
                int pp    = visit & 63;
                int kk    = visit >> 6;
                int pid   = base + pp;
                int nb    = inds[pp * 16 + kk];
                int brow  = (pid >= NB) ? NB : 0;
                float4 v  = *(const float4*)(xin + (size_t)(brow + nb) * 64
                                             + mega * 16 + w * 4);
                int col  = pp ^ (w * 8);
                int rowb = (w * 64 + kk) * 64 + col;
                gs[rowb + 0 * 16 * 64] = v.x;
                gs[rowb + 1 * 16 * 64] = v.y;
                gs[rowb + 2 * 16 * 64] = v.z;
                gs[rowb + 3 * 16 * 64] = v.w;
            }
        } else {
            #pragma unroll
            for (int rep = 0; rep < 4; ++rep) {
                int v  = rep * 256 + t;
                int pp = v & 63, kk = v >> 6;
                int pid = base + pp;
                const float* a = addf + ((size_t)pid * 16 + kk) * 3;
                gs[(0 * 16 + kk) * 64 + pp] = a[0];
                gs[(1 * 16 + kk) * 64 + pp] = a[1];
                gs[(2 * 16 + kk) * 64 + pp] = a[2];
                gs[(3 * 16 + kk) * 64 + pp] = 0.f;
            }
        }
        __syncthreads();

        const int nch = (mega < 4) ? 8 : 2;
        for (int i = 0; i < nch; ++i, ++cg) {
            const int buf = cg & 1;
            char* Pb = Pbase + buf * PTILEB;
            const uint32_t pbOff = (uint32_t)(buf * PTILEB);

            // ---- P compute: 2 channels x 4 m over 16 k (regs), fp16 pack ----
            #pragma unroll
            for (int cl = 0; cl < 2; ++cl) {
                int c_l = i * 2 + cl;
                int gb  = (c_l * 16) * 64 + (p ^ ((c_l >> 2) * 8));
                unsigned long long a0 = 0, a1 = 0;
                #pragma unroll
                for (int k = 0; k < 16; ++k) {
                    float gv = gs[gb + k * 64];
                    unsigned long long g2 = pack2(gv, gv);
                    fma2(a0, g2, wn2[k][0]);
                    fma2(a1, g2, wn2[k][1]);
                }
                float v0, v1, v2, v3;
                unpack2(a0, v0, v1); unpack2(a1, v2, v3);
                uint32_t col = ((uint32_t)(cl * 32 + mq * 8)) ^ pXor;
                *(uint2*)(Pb + p * PROWB + col) =
                    make_uint2(pack_f16x2(v0, v1), pack_f16x2(v2, v3));
            }

            // ---- B fragments: 4 coalesced LDG.128 (hide under sync+ldsm) ----
            const uint32_t* bc = bq + cg * 2048;
            uint4 u[4];
            #pragma unroll
            for (int q = 0; q < 4; ++q)
                u[q] = *(const uint4*)(bc + q * 128);

            __syncthreads();

            // ---- ldsm A (fp16, XOR addr) + 16 HMMA per warp ----
            #pragma unroll
            for (int mt = 0; mt < 2; ++mt) {
                int row  = wm * 32 + mt * 16 + arow_l;
                uint32_t X = ((uint32_t)(row >> 3) & 3) << 4;
                uint32_t abase = smb + pbOff + row * PROWB;
                #pragma unroll
                for (int ks = 0; ks < 2; ++ks) {
                    uint32_t a[4];
                    ldsm4(a, abase + (((uint32_t)(ks * 32) + ahi16) ^ X));
                    const uint4& u0 = u[ks * 2 + 0];
                    const uint4& u1 = u[ks * 2 + 1];
                    mma16(acc[mt][0], a, u0.x, u0.y);
                    mma16(acc[mt][1], a, u0.z, u0.w);
                    mma16(acc[mt][2], a, u1.x, u1.y);
                    mma16(acc[mt][3], a, u1.z, u1.w);
                }
            }
            // no trailing sync: P tiles double-buffered; the next chunk's sync
            // orders MMA(c) before the buffer is overwritten at chunk c+2.
        }
    }

    // ---- epilogue: bias + store (each warp 32p x 32o) ----
    #pragma unroll
    for (int mt = 0; mt < 2; ++mt) {
        int r = wm * 32 + mt * 16 + (l >> 2);
        #pragma unroll
        for (int nt = 0; nt < 4; ++nt) {
            int o  = wn4 * 32 + nt * 8 + 2 * (l & 3);
            float b0 = sm[OFF_BIAS + o], b1 = sm[OFF_BIAS + o + 1];
            int pid = base + r;
            *(float2*)(out + (size_t)pid * 128 + o) =
                make_float2(acc[mt][nt][0] + b0, acc[mt][nt][1] + b1);
            *(float2*)(out + (size_t)(pid + 8) * 128 + o) =
                make_float2(acc[mt][nt][2] + b0, acc[mt][nt][3] + b1);
        }
    }
}

extern "C" void kernel_launch(void* const* d_in, const int* in_sizes, int n_in,
                              void* d_out, int out_size) {
    const float* xin  = (const float*)d_in[0];
    const int*   nbr  = (const int*)d_in[1];
    const float* wng  = (const float*)d_in[2];
    const float* addf = (const float*)d_in[3];
    const float* W    = (const float*)d_in[4];
    const float* bias = (const float*)d_in[5];
    float*       out  = (float*)d_out;

    cudaFuncSetAttribute(pcl_kernel,
                         cudaFuncAttributeMaxDynamicSharedMemorySize, SMEM_BYTES);

    prep_kernel<<<NCHUNK, 128>>>(W);
    pcl_kernel<<<GRID, THREADS, SMEM_BYTES>>>(xin, nbr, wng, addf, bias, out);
}

// round 10
// speedup vs baseline: 3.5643x; 1.0943x over previous
#include <cuda_runtime.h>
#include <cstdint>

// ---------------------------------------------------------------------------
// PConvLinear, both stages on fp16 mma.sync (m16n8k16), fp32 accumulate.
//   out[p,o] = bias[o] + sum_f P[p,f] * W[o,f],  f = c*16 + m
//   P[p, c*16+m] = sum_{k<16} feat[p,k,c] * wn[p,k,m]
// Stage 1 (pconv): per point, per 16-ch group, per m-half: ONE m16n8k16 MMA
//   A = feat tile [c 16][k 16] fp16 in smem; B = wn frags in registers.
// Stage 2 (linear): P[64p x 256f] x Wfrag -> acc, as R9.
// 5 channel groups (80 ch padded), 3 syncs per group. 2 CTAs/SM.
// ---------------------------------------------------------------------------

#define NPTS 120000
#define NB   60000
#define TPB  64
#define THREADS 256
#define GRID (NPTS / TPB)      // 1875

// smem byte offsets
#define OFF_P    0             // 64 rows x 528 B   (P tile, 256 fp16 + pad)
#define OFF_A    33792         // 64 pts x 768 B    (feat tiles, 16r x 48B)
#define OFF_IND  82944         // 1024 ints
#define OFF_BIAS 87040         // 128 floats
#define SMEM_BYTES 87552       // -> 2 CTAs/SM

#define PROWB 528
#define AROWB 48
#define APTB  768

// W fragments: [g*16+s][wn4][q*128 + l*4]  (5*16*4*256 uint32)
__device__ uint32_t Wfrag[80 * 4 * 256];

__device__ __forceinline__ uint32_t smem_u32(const void* p) {
    uint32_t a;
    asm("{ .reg .u64 t; cvta.to.shared.u64 t, %1; cvt.u32.u64 %0, t; }"
        : "=r"(a) : "l"(p));
    return a;
}
__device__ __forceinline__ uint32_t pack_f16x2(float lo, float hi) {
    uint32_t r;
    asm("cvt.rn.f16x2.f32 %0, %1, %2;" : "=r"(r) : "f"(hi), "f"(lo));
    return r;
}
__device__ __forceinline__ void ldsm4(uint32_t r[4], uint32_t addr) {
    asm volatile("ldmatrix.sync.aligned.m8n8.x4.shared.b16 {%0,%1,%2,%3}, [%4];"
                 : "=r"(r[0]), "=r"(r[1]), "=r"(r[2]), "=r"(r[3]) : "r"(addr));
}
__device__ __forceinline__ void mma16(float c[4], const uint32_t a[4],
                                      uint32_t b0, uint32_t b1) {
    asm volatile(
        "mma.sync.aligned.m16n8k16.row.col.f32.f16.f16.f32 "
        "{%0,%1,%2,%3}, {%4,%5,%6,%7}, {%8,%9}, {%0,%1,%2,%3};"
        : "+f"(c[0]), "+f"(c[1]), "+f"(c[2]), "+f"(c[3])
        : "r"(a[0]), "r"(a[1]), "r"(a[2]), "r"(a[3]), "r"(b0), "r"(b1));
}

// ---- prep: analytic fp16 B fragments of W (f range 0..1279, 0-padded) ----
extern "C" __global__ void __launch_bounds__(128, 1)
prep_kernel(const float* __restrict__ W) {
    const int bg = blockIdx.x;           // g*16 + s
    const int t = threadIdx.x, l = t & 31, wn4 = t >> 5;
    const int f0 = (bg >> 4) * 256 + (bg & 15) * 16 + 2 * (l & 3);
    uint32_t r[8];
    #pragma unroll
    for (int nt = 0; nt < 4; ++nt) {
        int o = wn4 * 32 + nt * 8 + (l >> 2);
        const float* wr = W + (size_t)o * 1072;
        float v0 = (f0     < 1072) ? wr[f0]     : 0.f;
        float v1 = (f0 + 1 < 1072) ? wr[f0 + 1] : 0.f;
        float v2 = (f0 + 8 < 1072) ? wr[f0 + 8] : 0.f;
        float v3 = (f0 + 9 < 1072) ? wr[f0 + 9] : 0.f;
        r[nt * 2 + 0] = pack_f16x2(v0, v1);
        r[nt * 2 + 1] = pack_f16x2(v2, v3);
    }
    uint32_t* dst = Wfrag + (bg * 4 + wn4) * 256 + l * 4;
    *(uint4*)dst         = make_uint4(r[0], r[1], r[2], r[3]);
    *(uint4*)(dst + 128) = make_uint4(r[4], r[5], r[6], r[7]);
}

// ---- main ----
extern "C" __global__ void __launch_bounds__(THREADS, 2)
pcl_kernel(const float* __restrict__ xin,   // [2,60000,64]
           const int*   __restrict__ nbr,   // [2,60000,16]
           const float* __restrict__ wng,   // [2,60000,16,16]
           const float* __restrict__ addf,  // [2,60000,16,3]
           const float* __restrict__ bias,  // [128]
           float*       __restrict__ out)   // [2,60000,128]
{
    extern __shared__ __align__(16) char smc[];
    int*   inds = (int*)(smc + OFF_IND);
    float* bsm  = (float*)(smc + OFF_BIAS);

    const uint32_t smb = smem_u32(smc);
    const int t    = threadIdx.x;
    const int wid  = t >> 5;
    const int l    = t & 31;
    const int base = blockIdx.x * TPB;

    // main-GEMM roles: warp grid 2(m) x 4(n), 32p x 32o each
    const int wm  = wid & 1;
    const int wn4 = wid >> 1;

    if (t < 128) bsm[t] = bias[t];

    // ---- neighbor indices: 64 pts x 16 ----
    {
        int pt = base + (t >> 2);
        ((int4*)inds)[t] = *(const int4*)(nbr + (size_t)pt * 16 + (size_t)(t & 3) * 4);
    }

    // ---- pconv B fragments: warp's 8 points, per m-half, from wng ----
    uint32_t bw[8][2][2];
    {
        const int c2 = 2 * (l & 3);
        const int nl = l >> 2;
        #pragma unroll
        for (int j = 0; j < 8; ++j) {
            const float* wp = wng + (size_t)(base + wid * 8 + j) * 256;
            #pragma unroll
            for (int h = 0; h < 2; ++h) {
                int m = h * 8 + nl;
                bw[j][h][0] = pack_f16x2(wp[c2 * 16 + m],       wp[(c2 + 1) * 16 + m]);
                bw[j][h][1] = pack_f16x2(wp[(c2 + 8) * 16 + m], wp[(c2 + 9) * 16 + m]);
            }
        }
    }

    float acc[2][4][4];
    #pragma unroll
    for (int i = 0; i < 2; ++i)
        #pragma unroll
        for (int j = 0; j < 4; ++j)
            #pragma unroll
            for (int q = 0; q < 4; ++q) acc[i][j][q] = 0.f;

    // gather roles (fixed): w = channel quad, kp = k pair, pp per rep
    const int gw  = t & 3;
    const int gkp = (t >> 2) & 7;
    const int gp8 = t >> 5;

    for (int g = 0; g < 5; ++g) {
        __syncthreads();

        // ---- gather: feat tiles [c 16][k 16] fp16, rows AROWB apart ----
        #pragma unroll
        for (int rep = 0; rep < 8; ++rep) {
            int pp  = rep * 8 + gp8;
            int pid = base + pp;
            uint32_t* dst = (uint32_t*)(smc + OFF_A + pp * APTB + gw * 4 * AROWB) + gkp;
            if (g < 4) {
                int k0   = 2 * gkp;
                int nb0  = inds[pp * 16 + k0];
                int nb1  = inds[pp * 16 + k0 + 1];
                int brow = (pid >= NB) ? NB : 0;
                const float* s0 = xin + (size_t)(brow + nb0) * 64 + g * 16 + gw * 4;
                const float* s1 = xin + (size_t)(brow + nb1) * 64 + g * 16 + gw * 4;
                float4 va = *(const float4*)s0;
                float4 vb = *(const float4*)s1;
                dst[0 * 12] = pack_f16x2(va.x, vb.x);
                dst[1 * 12] = pack_f16x2(va.y, vb.y);
                dst[2 * 12] = pack_f16x2(va.z, vb.z);
                dst[3 * 12] = pack_f16x2(va.w, vb.w);
            } else {
                uint32_t w0 = 0, w1 = 0, w2 = 0;
                if (gw == 0) {
                    const float* a0 = addf + ((size_t)pid * 16 + 2 * gkp) * 3;
                    w0 = pack_f16x2(a0[0], a0[3]);
                    w1 = pack_f16x2(a0[1], a0[4]);
                    w2 = pack_f16x2(a0[2], a0[5]);
                }
                dst[0 * 12] = w0;
                dst[1 * 12] = w1;
                dst[2 * 12] = w2;
                dst[3 * 12] = 0;
            }
        }
        __syncthreads();

        // ---- pconv: per warp 8 points; 1 ldsm + 2 MMA + 4 STS per point ----
        {
            const uint32_t aoff = (uint32_t)((l & 15) * AROWB + (l >> 4) * 16);
            const int r  = l >> 2;
            const int mc = 2 * (l & 3);
            #pragma unroll
            for (int j = 0; j < 8; ++j) {
                uint32_t a[4];
                ldsm4(a, smb + OFF_A + (uint32_t)((wid * 8 + j) * APTB) + aoff);
                char* prow = smc + OFF_P + (wid * 8 + j) * PROWB;
                #pragma unroll
                for (int h = 0; h < 2; ++h) {
                    float c[4] = {0.f, 0.f, 0.f, 0.f};
                    mma16(c, a, bw[j][h][0], bw[j][h][1]);
                    int fl = r * 16 + h * 8 + mc;
                    *(uint32_t*)(prow + fl * 2)         = pack_f16x2(c[0], c[1]);
                    *(uint32_t*)(prow + (fl + 128) * 2) = pack_f16x2(c[2], c[3]);
                }
            }
        }
        __syncthreads();

        // ---- main GEMM: 16 k-steps over this group's 256-f P block ----
        {
            const uint32_t arow = smb + OFF_P +
                (uint32_t)((wm * 32 + (l & 15)) * PROWB + (l >> 4) * 16);
            const uint32_t* wfg = Wfrag + (size_t)(g * 16) * 1024 + wn4 * 256 + l * 4;
            #pragma unroll 4
            for (int s = 0; s < 16; ++s) {
                const uint32_t* wf = wfg + s * 1024;
                uint4 u0 = *(const uint4*)wf;
                uint4 u1 = *(const uint4*)(wf + 128);
                #pragma unroll
                for (int mt = 0; mt < 2; ++mt) {
                    uint32_t a[4];
                    ldsm4(a, arow + (uint32_t)(mt * 16 * PROWB + s * 32));
                    mma16(acc[mt][0], a, u0.x, u0.y);
                    mma16(acc[mt][1], a, u0.z, u0.w);
                    mma16(acc[mt][2], a, u1.x, u1.y);
                    mma16(acc[mt][3], a, u1.z, u1.w);
                }
            }
        }
    }

    // ---- epilogue: bias + store (each warp 32p x 32o) ----
    #pragma unroll
    for (int mt = 0; mt < 2; ++mt) {
        int r = wm * 32 + mt * 16 + (l >> 2);
        #pragma unroll
        for (int nt = 0; nt < 4; ++nt) {
            int o  = wn4 * 32 + nt * 8 + 2 * (l & 3);
            float b0 = bsm[o], b1 = bsm[o + 1];
            int pid = base + r;
            *(float2*)(out + (size_t)pid * 128 + o) =
                make_float2(acc[mt][nt][0] + b0, acc[mt][nt][1] + b1);
            *(float2*)(out + (size_t)(pid + 8) * 128 + o) =
                make_float2(acc[mt][nt][2] + b0, acc[mt][nt][3] + b1);
        }
    }
}

extern "C" void kernel_launch(void* const* d_in, const int* in_sizes, int n_in,
                              void* d_out, int out_size) {
    const float* xin  = (const float*)d_in[0];
    const int*   nbr  = (const int*)d_in[1];
    const float* wng  = (const float*)d_in[2];
    const float* addf = (const float*)d_in[3];
    const float* W    = (const float*)d_in[4];
    const float* bias = (const float*)d_in[5];
    float*       out  = (float*)d_out;

    cudaFuncSetAttribute(pcl_kernel,
                         cudaFuncAttributeMaxDynamicSharedMemorySize, SMEM_BYTES);

    prep_kernel<<<80, 128>>>(W);
    pcl_kernel<<<GRID, THREADS, SMEM_BYTES>>>(xin, nbr, wng, addf, bias, out);
}

// round 11
// speedup vs baseline: 3.9303x; 1.1027x over previous
#include <cuda_runtime.h>
#include <cstdint>

// ---------------------------------------------------------------------------
// PConvLinear, both stages on fp16 mma.sync (m16n8k16), fp32 accumulate.
//   out[p,o] = bias[o] + sum_f P[p,f] * W[o,f],  f = c*16 + m
//   P[p, c*16+m] = sum_{k<16} feat[p,k,c] * wn[p,k,m]
// R11: software-pipelined schedule. Per group:
//   R1: pconv(g)  [reads A, writes P]
//   sync
//   R2: mainGEMM(g) [reads P, Wfrag prefetch-1] interleaved with
//       gather(g+1) [writes A]   <- LDG latency hidden behind tensor work
//   sync
// Layouts identical to R10 (proven). 2 CTAs/SM.
// ---------------------------------------------------------------------------

#define NPTS 120000
#define NB   60000
#define TPB  64
#define THREADS 256
#define GRID (NPTS / TPB)      // 1875

// smem byte offsets
#define OFF_P    0             // 64 rows x 528 B   (P tile, 256 fp16 + pad)
#define OFF_A    33792         // 64 pts x 768 B    (feat tiles, 16r x 48B)
#define OFF_IND  82944         // 1024 ints
#define OFF_BIAS 87040         // 128 floats
#define SMEM_BYTES 87552       // -> 2 CTAs/SM

#define PROWB 528
#define AROWB 48
#define APTB  768

// W fragments: [g*16+s][wn4][q*128 + l*4]; padded one s-row for prefetch OOB
__device__ uint32_t Wfrag[81 * 1024];

__device__ __forceinline__ uint32_t smem_u32(const void* p) {
    uint32_t a;
    asm("{ .reg .u64 t; cvta.to.shared.u64 t, %1; cvt.u32.u64 %0, t; }"
        : "=r"(a) : "l"(p));
    return a;
}
__device__ __forceinline__ uint32_t pack_f16x2(float lo, float hi) {
    uint32_t r;
    asm("cvt.rn.f16x2.f32 %0, %1, %2;" : "=r"(r) : "f"(hi), "f"(lo));
    return r;
}
__device__ __forceinline__ void ldsm4(uint32_t r[4], uint32_t addr) {
    asm volatile("ldmatrix.sync.aligned.m8n8.x4.shared.b16 {%0,%1,%2,%3}, [%4];"
                 : "=r"(r[0]), "=r"(r[1]), "=r"(r[2]), "=r"(r[3]) : "r"(addr));
}
__device__ __forceinline__ void mma16(float c[4], const uint32_t a[4],
                                      uint32_t b0, uint32_t b1) {
    asm volatile(
        "mma.sync.aligned.m16n8k16.row.col.f32.f16.f16.f32 "
        "{%0,%1,%2,%3}, {%4,%5,%6,%7}, {%8,%9}, {%0,%1,%2,%3};"
        : "+f"(c[0]), "+f"(c[1]), "+f"(c[2]), "+f"(c[3])
        : "r"(a[0]), "r"(a[1]), "r"(a[2]), "r"(a[3]), "r"(b0), "r"(b1));
}

// ---- prep: analytic fp16 B fragments of W ----
extern "C" __global__ void __launch_bounds__(128, 1)
prep_kernel(const float* __restrict__ W) {
    const int bg = blockIdx.x;           // g*16 + s
    const int t = threadIdx.x, l = t & 31, wn4 = t >> 5;
    const int f0 = (bg >> 4) * 256 + (bg & 15) * 16 + 2 * (l & 3);
    uint32_t r[8];
    #pragma unroll
    for (int nt = 0; nt < 4; ++nt) {
        int o = wn4 * 32 + nt * 8 + (l >> 2);
        const float* wr = W + (size_t)o * 1072;
        float v0 = (f0     < 1072) ? wr[f0]     : 0.f;
        float v1 = (f0 + 1 < 1072) ? wr[f0 + 1] : 0.f;
        float v2 = (f0 + 8 < 1072) ? wr[f0 + 8] : 0.f;
        float v3 = (f0 + 9 < 1072) ? wr[f0 + 9] : 0.f;
        r[nt * 2 + 0] = pack_f16x2(v0, v1);
        r[nt * 2 + 1] = pack_f16x2(v2, v3);
    }
    uint32_t* dst = Wfrag + (bg * 4 + wn4) * 256 + l * 4;
    *(uint4*)dst         = make_uint4(r[0], r[1], r[2], r[3]);
    *(uint4*)(dst + 128) = make_uint4(r[4], r[5], r[6], r[7]);
}

// ---- main ----
extern "C" __global__ void __launch_bounds__(THREADS, 2)
pcl_kernel(const float* __restrict__ xin,   // [2,60000,64]
           const int*   __restrict__ nbr,   // [2,60000,16]
           const float* __restrict__ wng,   // [2,60000,16,16]
           const float* __restrict__ addf,  // [2,60000,16,3]
           const float* __restrict__ bias,  // [128]
           float*       __restrict__ out)   // [2,60000,128]
{
    extern __shared__ __align__(16) char smc[];
    int*   inds = (int*)(smc + OFF_IND);
    float* bsm  = (float*)(smc + OFF_BIAS);

    const uint32_t smb = smem_u32(smc);
    const int t    = threadIdx.x;
    const int wid  = t >> 5;
    const int l    = t & 31;
    const int base = blockIdx.x * TPB;

    // main-GEMM roles
    const int wm  = wid & 1;
    const int wn4 = wid >> 1;

    if (t < 128) bsm[t] = bias[t];

    // ---- neighbor indices: 64 pts x 16 ----
    {
        int pt = base + (t >> 2);
        ((int4*)inds)[t] = *(const int4*)(nbr + (size_t)pt * 16 + (size_t)(t & 3) * 4);
    }

    // ---- pconv B fragments: warp's 8 points, per m-half, from wng ----
    uint32_t bw[8][2][2];
    {
        const int c2 = 2 * (l & 3);
        const int nl = l >> 2;
        #pragma unroll
        for (int j = 0; j < 8; ++j) {
            const float* wp = wng + (size_t)(base + wid * 8 + j) * 256;
            #pragma unroll
            for (int h = 0; h < 2; ++h) {
                int m = h * 8 + nl;
                bw[j][h][0] = pack_f16x2(wp[c2 * 16 + m],       wp[(c2 + 1) * 16 + m]);
                bw[j][h][1] = pack_f16x2(wp[(c2 + 8) * 16 + m], wp[(c2 + 9) * 16 + m]);
            }
        }
    }

    float acc[2][4][4];
    #pragma unroll
    for (int i = 0; i < 2; ++i)
        #pragma unroll
        for (int j = 0; j < 4; ++j)
            #pragma unroll
            for (int q = 0; q < 4; ++q) acc[i][j][q] = 0.f;

    // gather roles (fixed)
    const int gw  = t & 3;
    const int gkp = (t >> 2) & 7;
    const int gp8 = t >> 5;

    // gather rep helpers (gg = target group, rep 0..7)
    auto gatherLDG = [&](int gg, int rep, float4& va, float4& vb) {
        int pp  = rep * 8 + gp8;
        int pid = base + pp;
        if (gg < 4) {
            int k0   = 2 * gkp;
            int nb0  = inds[pp * 16 + k0];
            int nb1  = inds[pp * 16 + k0 + 1];
            int brow = (pid >= NB) ? NB : 0;
            va = *(const float4*)(xin + (size_t)(brow + nb0) * 64 + gg * 16 + gw * 4);
            vb = *(const float4*)(xin + (size_t)(brow + nb1) * 64 + gg * 16 + gw * 4);
        } else {
            va = make_float4(0.f, 0.f, 0.f, 0.f);
            vb = make_float4(0.f, 0.f, 0.f, 0.f);
            if (gw == 0) {
                const float* a0 = addf + ((size_t)pid * 16 + 2 * gkp) * 3;
                va.x = a0[0]; va.y = a0[1]; va.z = a0[2];
                vb.x = a0[3]; vb.y = a0[4]; vb.z = a0[5];
            }
        }
    };
    auto gatherSTS = [&](int rep, const float4& va, const float4& vb) {
        int pp = rep * 8 + gp8;
        uint32_t* dst = (uint32_t*)(smc + OFF_A + pp * APTB + gw * 4 * AROWB) + gkp;
        dst[0 * 12] = pack_f16x2(va.x, vb.x);
        dst[1 * 12] = pack_f16x2(va.y, vb.y);
        dst[2 * 12] = pack_f16x2(va.z, vb.z);
        dst[3 * 12] = pack_f16x2(va.w, vb.w);
    };

    __syncthreads();   // inds visible

    // ---- prologue gather: group 0 ----
    #pragma unroll
    for (int rep = 0; rep < 8; ++rep) {
        float4 va, vb;
        gatherLDG(0, rep, va, vb);
        gatherSTS(rep, va, vb);
    }
    __syncthreads();   // A ready

    for (int g = 0; g < 5; ++g) {
        // ---- R1: pconv(g): per warp 8 points; 1 ldsm + 2 MMA + 4 STS ----
        {
            const uint32_t aoff = (uint32_t)((l & 15) * AROWB + (l >> 4) * 16);
            const int r  = l >> 2;
            const int mc = 2 * (l & 3);
            #pragma unroll
            for (int j = 0; j < 8; ++j) {
                uint32_t a[4];
                ldsm4(a, smb + OFF_A + (uint32_t)((wid * 8 + j) * APTB) + aoff);
                char* prow = smc + OFF_P + (wid * 8 + j) * PROWB;
                #pragma unroll
                for (int h = 0; h < 2; ++h) {
                    float c[4] = {0.f, 0.f, 0.f, 0.f};
                    mma16(c, a, bw[j][h][0], bw[j][h][1]);
                    int fl = r * 16 + h * 8 + mc;
                    *(uint32_t*)(prow + fl * 2)         = pack_f16x2(c[0], c[1]);
                    *(uint32_t*)(prow + (fl + 128) * 2) = pack_f16x2(c[2], c[3]);
                }
            }
        }
        __syncthreads();   // P ready; A free

        // ---- R2: mainGEMM(g) + gather(g+1) interleaved ----
        {
            const uint32_t arow = smb + OFF_P +
                (uint32_t)((wm * 32 + (l & 15)) * PROWB + (l >> 4) * 16);
            const uint32_t* wfg = Wfrag + (size_t)(g * 16) * 1024 + wn4 * 256 + l * 4;
            uint4 u0c = *(const uint4*)wfg;
            uint4 u1c = *(const uint4*)(wfg + 128);
            #pragma unroll
            for (int blk = 0; blk < 4; ++blk) {
                float4 va0, vb0, va1, vb1;
                if (g < 4) {
                    gatherLDG(g + 1, blk * 2 + 0, va0, vb0);
                    gatherLDG(g + 1, blk * 2 + 1, va1, vb1);
                }
                #pragma unroll
                for (int ss = 0; ss < 4; ++ss) {
                    int s = blk * 4 + ss;
                    const uint32_t* wfn = wfg + (s + 1) * 1024;  // padded array
                    uint4 u0n = *(const uint4*)wfn;
                    uint4 u1n = *(const uint4*)(wfn + 128);
                    #pragma unroll
                    for (int mt = 0; mt < 2; ++mt) {
                        uint32_t a[4];
                        ldsm4(a, arow + (uint32_t)(mt * 16 * PROWB + s * 32));
                        mma16(acc[mt][0], a, u0c.x, u0c.y);
                        mma16(acc[mt][1], a, u0c.z, u0c.w);
                        mma16(acc[mt][2], a, u1c.x, u1c.y);
                        mma16(acc[mt][3], a, u1c.z, u1c.w);
                    }
                    u0c = u0n; u1c = u1n;
                }
                if (g < 4) {
                    gatherSTS(blk * 2 + 0, va0, vb0);
                    gatherSTS(blk * 2 + 1, va1, vb1);
                }
            }
        }
        __syncthreads();   // A ready for pconv(g+1); P free
    }

    // ---- epilogue: bias + store (each warp 32p x 32o) ----
    #pragma unroll
    for (int mt = 0; mt < 2; ++mt) {
        int r = wm * 32 + mt * 16 + (l >> 2);
        #pragma unroll
        for (int nt = 0; nt < 4; ++nt) {
            int o  = wn4 * 32 + nt * 8 + 2 * (l & 3);
            float b0 = bsm[o], b1 = bsm[o + 1];
            int pid = base + r;
            *(float2*)(out + (size_t)pid * 128 + o) =
                make_float2(acc[mt][nt][0] + b0, acc[mt][nt][1] + b1);
            *(float2*)(out + (size_t)(pid + 8) * 128 + o) =
                make_float2(acc[mt][nt][2] + b0, acc[mt][nt][3] + b1);
        }
    }
}

extern "C" void kernel_launch(void* const* d_in, const int* in_sizes, int n_in,
                              void* d_out, int out_size) {
    const float* xin  = (const float*)d_in[0];
    const int*   nbr  = (const int*)d_in[1];
    const float* wng  = (const float*)d_in[2];
    const float* addf = (const float*)d_in[3];
    const float* W    = (const float*)d_in[4];
    const float* bias = (const float*)d_in[5];
    float*       out  = (float*)d_out;

    cudaFuncSetAttribute(pcl_kernel,
                         cudaFuncAttributeMaxDynamicSharedMemorySize, SMEM_BYTES);

    prep_kernel<<<80, 128>>>(W);
    pcl_kernel<<<GRID, THREADS, SMEM_BYTES>>>(xin, nbr, wng, addf, bias, out);
}